// round 5
// baseline (speedup 1.0000x reference)
#include <cuda_runtime.h>

#define NXD 1024
#define NYD 1024
#define BD  16
#define NP  (NXD * NYD)

// ---- generic (boundary) helpers: edge-order-2 one-sided stencils ----
__device__ __forceinline__ void gcoef1(int i, int N, int idx[3], float c[3], int& n) {
    if (i == 0)          { idx[0]=0;   idx[1]=1;   idx[2]=2;   c[0]=-1.5f; c[1]= 2.0f; c[2]=-0.5f; n=3; }
    else if (i == N - 1) { idx[0]=N-1; idx[1]=N-2; idx[2]=N-3; c[0]= 1.5f; c[1]=-2.0f; c[2]= 0.5f; n=3; }
    else                 { idx[0]=i-1; idx[1]=i+1; c[0]=-0.5f; c[1]=0.5f; n=2; }
}

__device__ __forceinline__ void gcoef2(int i, int N, int idx[4], float c[4], int& n) {
    if (i == 0)          { idx[0]=0;   idx[1]=1;   idx[2]=2;   idx[3]=3;   c[0]=2.0f; c[1]=-5.0f; c[2]=4.0f; c[3]=-1.0f; n=4; }
    else if (i == N - 1) { idx[0]=N-1; idx[1]=N-2; idx[2]=N-3; idx[3]=N-4; c[0]=2.0f; c[1]=-5.0f; c[2]=4.0f; c[3]=-1.0f; n=4; }
    else                 { idx[0]=i-1; idx[1]=i;   idx[2]=i+1; c[0]=1.0f; c[1]=-2.0f; c[2]=1.0f; n=3; }
}

__device__ float generic_df(const float* __restrict__ Fb,
                            const float* __restrict__ A0, const float* __restrict__ A1,
                            const float* __restrict__ B0, const float* __restrict__ B1,
                            const float* __restrict__ B2, int x, int y)
{
    int ix1[3]; float cx1[3]; int nx1;
    int iy1[3]; float cy1[3]; int ny1;
    gcoef1(x, NXD, ix1, cx1, nx1);
    gcoef1(y, NYD, iy1, cy1, ny1);

    int ix2[4]; float cx2[4]; int nx2;
    int iy2[4]; float cy2[4]; int ny2;
    gcoef2(x, NXD, ix2, cx2, nx2);
    gcoef2(y, NYD, iy2, cy2, ny2);

    float ga = 0.0f;
    #pragma unroll
    for (int j = 0; j < 3; ++j)
        if (j < nx1) { int k = ix1[j] * NYD + y; ga += cx1[j] * __ldg(&A0[k]) * __ldg(&Fb[k]); }
    #pragma unroll
    for (int j = 0; j < 3; ++j)
        if (j < ny1) { int k = x * NYD + iy1[j]; ga += cy1[j] * __ldg(&A1[k]) * __ldg(&Fb[k]); }

    float gb = 0.0f;
    #pragma unroll
    for (int j = 0; j < 4; ++j)
        if (j < nx2) { int k = ix2[j] * NYD + y; gb += cx2[j] * __ldg(&B0[k]) * __ldg(&Fb[k]); }
    #pragma unroll
    for (int j = 0; j < 4; ++j)
        if (j < ny2) { int k = x * NYD + iy2[j]; gb += cy2[j] * __ldg(&B1[k]) * __ldg(&Fb[k]); }

    float gc = 0.0f;
    #pragma unroll
    for (int j = 0; j < 3; ++j)
        if (j < nx1) {
            float acc = 0.0f;
            #pragma unroll
            for (int k = 0; k < 3; ++k)
                if (k < ny1) {
                    int idx = ix1[j] * NYD + iy1[k];
                    acc += cy1[k] * __ldg(&B2[idx]) * __ldg(&Fb[idx]);
                }
            gc += cx1[j] * acc;
        }
    return -ga + 0.5f * gb + gc;
}

// ---- main kernel: 4 y-points/thread, shuffle halos, hoisted 9-pt weights ----
__global__ void __launch_bounds__(128) fp2d_kernel(
    const float* __restrict__ f,      // [B, NX, NY]
    const float* __restrict__ Agrid,  // [2, NX, NY]
    const float* __restrict__ Bgrid,  // [3, NX, NY]
    const float* __restrict__ dt,     // [B]
    float* __restrict__ out)          // [B, NX, NY]
{
    const int lane = threadIdx.x;                      // 0..31, warp = y strip
    const int y0   = (blockIdx.x * 32 + lane) * 4;     // multiple of 4
    const int x    = blockIdx.y * 4 + threadIdx.y;

    const float* __restrict__ A0 = Agrid;
    const float* __restrict__ A1 = Agrid + NP;
    const float* __restrict__ B0 = Bgrid;
    const float* __restrict__ B1 = Bgrid + NP;
    const float* __restrict__ B2 = Bgrid + 2 * NP;

    // clamped row/col indices (only matter for boundary threads, whose results
    // get overwritten by the generic pass below)
    const int xm = (x == 0)        ? 0        : x - 1;
    const int xp = (x == NXD - 1)  ? NXD - 1  : x + 1;
    const int yl = (y0 == 0)       ? 0        : y0 - 1;          // left halo col
    const int yr = (y0 + 4 > NYD-1)? NYD - 1  : y0 + 4;          // right halo col

    const int bmi = xm * NYD + y0;   // clamped rows for loads
    const int bci = x  * NYD + y0;
    const int bpi = xp * NYD + y0;
    const int loff = yl - y0;        // -1 (or 0 at edge)
    const int roff = yr - y0;        //  4 (or 3 at edge)

    // ---- batch-invariant grid loads / weights ----
    float a1v[6], b1v[6], b2mv[6], b2pv[6];
    {
        float4 t;
        t = __ldg((const float4*)&A1[bci]);  a1v[1]=t.x; a1v[2]=t.y; a1v[3]=t.z; a1v[4]=t.w;
        a1v[0] = __ldg(&A1[x * NYD + yl]);   a1v[5] = __ldg(&A1[x * NYD + yr]);
        t = __ldg((const float4*)&B1[bci]);  b1v[1]=t.x; b1v[2]=t.y; b1v[3]=t.z; b1v[4]=t.w;
        b1v[0] = __ldg(&B1[x * NYD + yl]);   b1v[5] = __ldg(&B1[x * NYD + yr]);
        t = __ldg((const float4*)&B2[bmi]);  b2mv[1]=t.x; b2mv[2]=t.y; b2mv[3]=t.z; b2mv[4]=t.w;
        b2mv[0] = __ldg(&B2[xm * NYD + yl]); b2mv[5] = __ldg(&B2[xm * NYD + yr]);
        t = __ldg((const float4*)&B2[bpi]);  b2pv[1]=t.x; b2pv[2]=t.y; b2pv[3]=t.z; b2pv[4]=t.w;
        b2pv[0] = __ldg(&B2[xp * NYD + yl]); b2pv[5] = __ldg(&B2[xp * NYD + yr]);
    }
    const float4 a0m = __ldg((const float4*)&A0[bmi]);
    const float4 a0p = __ldg((const float4*)&A0[bpi]);
    const float4 b0m = __ldg((const float4*)&B0[bmi]);
    const float4 b0c = __ldg((const float4*)&B0[bci]);
    const float4 b0p = __ldg((const float4*)&B0[bpi]);

    float wmm[4], wm0[4], wmp[4], w0m[4], w00[4], w0p[4], wpm[4], wp0[4], wpp[4];
    {
        const float a0ma[4] = {a0m.x, a0m.y, a0m.z, a0m.w};
        const float a0pa[4] = {a0p.x, a0p.y, a0p.z, a0p.w};
        const float b0ma[4] = {b0m.x, b0m.y, b0m.z, b0m.w};
        const float b0ca[4] = {b0c.x, b0c.y, b0c.z, b0c.w};
        const float b0pa[4] = {b0p.x, b0p.y, b0p.z, b0p.w};
        #pragma unroll
        for (int s = 0; s < 4; ++s) {
            wmm[s] =  0.25f * b2mv[s];
            wmp[s] = -0.25f * b2mv[s + 2];
            wpm[s] = -0.25f * b2pv[s];
            wpp[s] =  0.25f * b2pv[s + 2];
            wm0[s] =  0.5f * (a0ma[s] + b0ma[s]);
            wp0[s] =  0.5f * (b0pa[s] - a0pa[s]);
            w0m[s] =  0.5f * (a1v[s] + b1v[s]);
            w0p[s] =  0.5f * (b1v[s + 2] - a1v[s + 2]);
            w00[s] = -(b0ca[s] + b1v[s + 1]);
        }
    }

    const unsigned FULL = 0xffffffffu;
    const int obase = x * NYD + y0;

    // ---- fast path: all threads (boundary threads produce garbage, fixed later) ----
    #pragma unroll 4
    for (int b = 0; b < BD; ++b) {
        const float* __restrict__ Fb = f + b * NP;
        const float dtb = __ldg(&dt[b]);

        float4 vm = __ldg((const float4*)&Fb[bmi]);
        float4 vc = __ldg((const float4*)&Fb[bci]);
        float4 vp = __ldg((const float4*)&Fb[bpi]);

        float Lm = __shfl_up_sync(FULL, vm.w, 1);
        float Lc = __shfl_up_sync(FULL, vc.w, 1);
        float Lp = __shfl_up_sync(FULL, vp.w, 1);
        float Rm = __shfl_down_sync(FULL, vm.x, 1);
        float Rc = __shfl_down_sync(FULL, vc.x, 1);
        float Rp = __shfl_down_sync(FULL, vp.x, 1);
        if (lane == 0) {
            Lm = __ldg(&Fb[bmi + loff]);
            Lc = __ldg(&Fb[bci + loff]);
            Lp = __ldg(&Fb[bpi + loff]);
        }
        if (lane == 31) {
            Rm = __ldg(&Fb[bmi + roff]);
            Rc = __ldg(&Fb[bci + roff]);
            Rp = __ldg(&Fb[bpi + roff]);
        }

        const float dm[6] = {Lm, vm.x, vm.y, vm.z, vm.w, Rm};
        const float dc[6] = {Lc, vc.x, vc.y, vc.z, vc.w, Rc};
        const float dp[6] = {Lp, vp.x, vp.y, vp.z, vp.w, Rp};

        float o[4];
        #pragma unroll
        for (int s = 0; s < 4; ++s) {
            float df;
            df = wmm[s] * dm[s];
            df = fmaf(wm0[s], dm[s + 1], df);
            df = fmaf(wmp[s], dm[s + 2], df);
            df = fmaf(w0m[s], dc[s],     df);
            df = fmaf(w00[s], dc[s + 1], df);
            df = fmaf(w0p[s], dc[s + 2], df);
            df = fmaf(wpm[s], dp[s],     df);
            df = fmaf(wp0[s], dp[s + 1], df);
            df = fmaf(wpp[s], dp[s + 2], df);
            o[s] = fmaxf(fmaf(df, dtb, dc[s + 1]), 0.0f);
        }
        float4 ov = make_float4(o[0], o[1], o[2], o[3]);
        *(float4*)&out[b * NP + obase] = ov;
    }

    // ---- boundary fix-up: ~1% of threads recompute generically and overwrite ----
    const bool is_bnd = (x == 0) | (x == NXD - 1) | (y0 == 0) | (y0 == NYD - 4);
    if (is_bnd) {
        for (int b = 0; b < BD; ++b) {
            const float* __restrict__ Fb = f + b * NP;
            const float dtb = __ldg(&dt[b]);
            #pragma unroll
            for (int s = 0; s < 4; ++s) {
                const int y = y0 + s;
                float df = generic_df(Fb, A0, A1, B0, B1, B2, x, y);
                float v = fmaf(df, dtb, __ldg(&Fb[x * NYD + y]));
                out[b * NP + x * NYD + y] = fmaxf(v, 0.0f);
            }
        }
    }
}

extern "C" void kernel_launch(void* const* d_in, const int* in_sizes, int n_in,
                              void* d_out, int out_size) {
    const float* f  = (const float*)d_in[0];
    const float* Ag = (const float*)d_in[1];
    const float* Bg = (const float*)d_in[2];
    const float* dt = (const float*)d_in[3];
    float* out = (float*)d_out;

    dim3 block(32, 4, 1);
    dim3 grid(NYD / 128, NXD / 4, 1);   // 4 y-points per thread
    fp2d_kernel<<<grid, block>>>(f, Ag, Bg, dt, out);
}

// round 7
// speedup vs baseline: 2.4064x; 2.4064x over previous
#include <cuda_runtime.h>

#define NXD 1024
#define NYD 1024
#define BD  16
#define NP  (NXD * NYD)

// ---- generic stencil helpers (used by boundary kernel only) ----
__device__ __forceinline__ void gcoef1(int i, int N, int idx[3], float c[3], int& n) {
    if (i == 0)          { idx[0]=0;   idx[1]=1;   idx[2]=2;   c[0]=-1.5f; c[1]= 2.0f; c[2]=-0.5f; n=3; }
    else if (i == N - 1) { idx[0]=N-1; idx[1]=N-2; idx[2]=N-3; c[0]= 1.5f; c[1]=-2.0f; c[2]= 0.5f; n=3; }
    else                 { idx[0]=i-1; idx[1]=i+1; c[0]=-0.5f; c[1]=0.5f; n=2; }
}

__device__ __forceinline__ void gcoef2(int i, int N, int idx[4], float c[4], int& n) {
    if (i == 0)          { idx[0]=0;   idx[1]=1;   idx[2]=2;   idx[3]=3;   c[0]=2.0f; c[1]=-5.0f; c[2]=4.0f; c[3]=-1.0f; n=4; }
    else if (i == N - 1) { idx[0]=N-1; idx[1]=N-2; idx[2]=N-3; idx[3]=N-4; c[0]=2.0f; c[1]=-5.0f; c[2]=4.0f; c[3]=-1.0f; n=4; }
    else                 { idx[0]=i-1; idx[1]=i;   idx[2]=i+1; c[0]=1.0f; c[1]=-2.0f; c[2]=1.0f; n=3; }
}

__device__ float generic_df(const float* __restrict__ Fb,
                            const float* __restrict__ A0, const float* __restrict__ A1,
                            const float* __restrict__ B0, const float* __restrict__ B1,
                            const float* __restrict__ B2, int x, int y)
{
    int ix1[3]; float cx1[3]; int nx1;
    int iy1[3]; float cy1[3]; int ny1;
    gcoef1(x, NXD, ix1, cx1, nx1);
    gcoef1(y, NYD, iy1, cy1, ny1);

    int ix2[4]; float cx2[4]; int nx2;
    int iy2[4]; float cy2[4]; int ny2;
    gcoef2(x, NXD, ix2, cx2, nx2);
    gcoef2(y, NYD, iy2, cy2, ny2);

    float ga = 0.0f;
    #pragma unroll
    for (int j = 0; j < 3; ++j)
        if (j < nx1) { int k = ix1[j] * NYD + y; ga += cx1[j] * __ldg(&A0[k]) * __ldg(&Fb[k]); }
    #pragma unroll
    for (int j = 0; j < 3; ++j)
        if (j < ny1) { int k = x * NYD + iy1[j]; ga += cy1[j] * __ldg(&A1[k]) * __ldg(&Fb[k]); }

    float gb = 0.0f;
    #pragma unroll
    for (int j = 0; j < 4; ++j)
        if (j < nx2) { int k = ix2[j] * NYD + y; gb += cx2[j] * __ldg(&B0[k]) * __ldg(&Fb[k]); }
    #pragma unroll
    for (int j = 0; j < 4; ++j)
        if (j < ny2) { int k = x * NYD + iy2[j]; gb += cy2[j] * __ldg(&B1[k]) * __ldg(&Fb[k]); }

    float gc = 0.0f;
    #pragma unroll
    for (int j = 0; j < 3; ++j)
        if (j < nx1) {
            float acc = 0.0f;
            #pragma unroll
            for (int k = 0; k < 3; ++k)
                if (k < ny1) {
                    int idx = ix1[j] * NYD + iy1[k];
                    acc += cy1[k] * __ldg(&B2[idx]) * __ldg(&Fb[idx]);
                }
            gc += cx1[j] * acc;
        }
    return -ga + 0.5f * gb + gc;
}

// ================= interior kernel: x in [1,1022], y quads [4,1016] =================
__global__ void __launch_bounds__(128, 6) fp2d_interior(
    const float* __restrict__ f,      // [B, NX, NY]
    const float* __restrict__ Agrid,  // [2, NX, NY]
    const float* __restrict__ Bgrid,  // [3, NX, NY]
    const float* __restrict__ dt,     // [B]
    float* __restrict__ out)          // [B, NX, NY]
{
    const int q  = 1 + blockIdx.x * 32 + threadIdx.x;  // quad index, want [1,254]
    const int x  = 1 + blockIdx.y * 4 + threadIdx.y;   // want [1,1022]
    if (q > 254 || x > 1022) return;
    const int y0 = q * 4;                              // y0 in [4,1016], 16B aligned

    const float* __restrict__ A0 = Agrid;
    const float* __restrict__ A1 = Agrid + NP;
    const float* __restrict__ B0 = Bgrid;
    const float* __restrict__ B1 = Bgrid + NP;
    const float* __restrict__ B2 = Bgrid + 2 * NP;

    const int bm = (x - 1) * NYD + y0;
    const int bc =  x      * NYD + y0;
    const int bp = (x + 1) * NYD + y0;

    // ---- batch-invariant grid loads: 6-val rows as float2 + float4 + float2 ----
    float b2m[6], b2p[6], a1v[6], b1v[6];
    {
        float2 e0; float4 m; float2 e1;
        e0 = __ldg((const float2*)&B2[bm - 2]); m = __ldg((const float4*)&B2[bm]); e1 = __ldg((const float2*)&B2[bm + 4]);
        b2m[0]=e0.y; b2m[1]=m.x; b2m[2]=m.y; b2m[3]=m.z; b2m[4]=m.w; b2m[5]=e1.x;
        e0 = __ldg((const float2*)&B2[bp - 2]); m = __ldg((const float4*)&B2[bp]); e1 = __ldg((const float2*)&B2[bp + 4]);
        b2p[0]=e0.y; b2p[1]=m.x; b2p[2]=m.y; b2p[3]=m.z; b2p[4]=m.w; b2p[5]=e1.x;
        e0 = __ldg((const float2*)&A1[bc - 2]); m = __ldg((const float4*)&A1[bc]); e1 = __ldg((const float2*)&A1[bc + 4]);
        a1v[0]=e0.y; a1v[1]=m.x; a1v[2]=m.y; a1v[3]=m.z; a1v[4]=m.w; a1v[5]=e1.x;
        e0 = __ldg((const float2*)&B1[bc - 2]); m = __ldg((const float4*)&B1[bc]); e1 = __ldg((const float2*)&B1[bc + 4]);
        b1v[0]=e0.y; b1v[1]=m.x; b1v[2]=m.y; b1v[3]=m.z; b1v[4]=m.w; b1v[5]=e1.x;
    }
    const float4 a0m = __ldg((const float4*)&A0[bm]);
    const float4 a0p = __ldg((const float4*)&A0[bp]);
    const float4 b0m = __ldg((const float4*)&B0[bm]);
    const float4 b0c = __ldg((const float4*)&B0[bc]);
    const float4 b0p = __ldg((const float4*)&B0[bp]);

    // ---- fold into 9 weights per point ----
    float wmm[4], wm0[4], wmp[4], w0m[4], w00[4], w0p[4], wpm[4], wp0[4], wpp[4];
    {
        const float a0ma[4] = {a0m.x, a0m.y, a0m.z, a0m.w};
        const float a0pa[4] = {a0p.x, a0p.y, a0p.z, a0p.w};
        const float b0ma[4] = {b0m.x, b0m.y, b0m.z, b0m.w};
        const float b0ca[4] = {b0c.x, b0c.y, b0c.z, b0c.w};
        const float b0pa[4] = {b0p.x, b0p.y, b0p.z, b0p.w};
        #pragma unroll
        for (int s = 0; s < 4; ++s) {
            wmm[s] =  0.25f * b2m[s];
            wmp[s] = -0.25f * b2m[s + 2];
            wpm[s] = -0.25f * b2p[s];
            wpp[s] =  0.25f * b2p[s + 2];
            w0m[s] =  0.5f * (a1v[s] + b1v[s]);
            w0p[s] =  0.5f * (b1v[s + 2] - a1v[s + 2]);
            wm0[s] =  0.5f * (a0ma[s] + b0ma[s]);
            wp0[s] =  0.5f * (b0pa[s] - a0pa[s]);
            w00[s] = -(b0ca[s] + b1v[s + 1]);
        }
    }

    // ---- batch loop: 9 vector loads -> 36 FMA -> 1 STG.128 ----
    const float* __restrict__ Fb = f;
    float* __restrict__ Ob = out + bc;
    for (int b = 0; b < BD; ++b, Fb += NP, Ob += NP) {
        const float dtb = __ldg(&dt[b]);

        float2 m2 = __ldg((const float2*)&Fb[bm - 2]);
        float4 m4 = __ldg((const float4*)&Fb[bm]);
        float2 m6 = __ldg((const float2*)&Fb[bm + 4]);
        float2 c2 = __ldg((const float2*)&Fb[bc - 2]);
        float4 c4 = __ldg((const float4*)&Fb[bc]);
        float2 c6 = __ldg((const float2*)&Fb[bc + 4]);
        float2 p2 = __ldg((const float2*)&Fb[bp - 2]);
        float4 p4 = __ldg((const float4*)&Fb[bp]);
        float2 p6 = __ldg((const float2*)&Fb[bp + 4]);

        const float dm[6] = {m2.y, m4.x, m4.y, m4.z, m4.w, m6.x};
        const float dc[6] = {c2.y, c4.x, c4.y, c4.z, c4.w, c6.x};
        const float dp[6] = {p2.y, p4.x, p4.y, p4.z, p4.w, p6.x};

        float o[4];
        #pragma unroll
        for (int s = 0; s < 4; ++s) {
            float df;
            df = wmm[s] * dm[s];
            df = fmaf(wm0[s], dm[s + 1], df);
            df = fmaf(wmp[s], dm[s + 2], df);
            df = fmaf(w0m[s], dc[s],     df);
            df = fmaf(w00[s], dc[s + 1], df);
            df = fmaf(w0p[s], dc[s + 2], df);
            df = fmaf(wpm[s], dp[s],     df);
            df = fmaf(wp0[s], dp[s + 1], df);
            df = fmaf(wpp[s], dp[s + 2], df);
            o[s] = fmaxf(fmaf(df, dtb, dc[s + 1]), 0.0f);
        }
        *(float4*)Ob = make_float4(o[0], o[1], o[2], o[3]);
    }
}

// ================= boundary kernel: the 10224 points the interior kernel skips =================
// y in {0,1,2,3,1020,1021,1022,1023} for all x  (8192 pts)
// x in {0,1023} for y in [4,1019]               (2032 pts)
#define NBPTS 10224

__global__ void __launch_bounds__(128) fp2d_boundary(
    const float* __restrict__ f,
    const float* __restrict__ Agrid,
    const float* __restrict__ Bgrid,
    const float* __restrict__ dt,
    float* __restrict__ out)
{
    const int idx = blockIdx.x * 128 + threadIdx.x;
    if (idx >= NBPTS) return;
    const int b = blockIdx.y;

    int x, y;
    if (idx < 8192) {
        x = idx >> 3;
        int r = idx & 7;
        y = (r < 4) ? r : (1016 + r);
    } else {
        int r = idx - 8192;
        x = (r & 1) ? 1023 : 0;
        y = 4 + (r >> 1);
    }

    const float* __restrict__ A0 = Agrid;
    const float* __restrict__ A1 = Agrid + NP;
    const float* __restrict__ B0 = Bgrid;
    const float* __restrict__ B1 = Bgrid + NP;
    const float* __restrict__ B2 = Bgrid + 2 * NP;

    const float* __restrict__ Fb = f + b * NP;
    const float df = generic_df(Fb, A0, A1, B0, B1, B2, x, y);
    const int k = x * NYD + y;
    float v = fmaf(df, __ldg(&dt[b]), __ldg(&Fb[k]));
    out[b * NP + k] = fmaxf(v, 0.0f);
}

extern "C" void kernel_launch(void* const* d_in, const int* in_sizes, int n_in,
                              void* d_out, int out_size) {
    const float* f  = (const float*)d_in[0];
    const float* Ag = (const float*)d_in[1];
    const float* Bg = (const float*)d_in[2];
    const float* dt = (const float*)d_in[3];
    float* out = (float*)d_out;

    dim3 bblock(128, 1, 1);
    dim3 bgrid((NBPTS + 127) / 128, BD, 1);
    fp2d_boundary<<<bgrid, bblock>>>(f, Ag, Bg, dt, out);

    dim3 iblock(32, 4, 1);
    dim3 igrid(8, 256, 1);
    fp2d_interior<<<igrid, iblock>>>(f, Ag, Bg, dt, out);
}